// round 10
// baseline (speedup 1.0000x reference)
#include <cuda_runtime.h>
#include <cuda_bf16.h>
#include <cstdint>

// 8 lanes per edge, 4 edges per warp.
// R9: occupancy push — dropped createpolicy (measured neutral), forced
// regs<=36 via __launch_bounds__(256,7) for 7 CTAs/SM (87.5% occupancy).
// Rows via __ldg (read-only path), indices via __ldcs (streaming),
// output via st.global.cs (streaming).
// blockIdx.y selects edge type:
//   y=0: clicks (user->item), y=1: clickedby (item->user), y=2: follows (user->user)
// Index arrays are int32 (JAX x64-disabled coerces int64 -> int32).

__device__ __forceinline__ void stg_stream_f32(float* p, float v) {
    asm volatile("st.global.cs.f32 [%0], %1;" :: "l"(p), "f"(v) : "memory");
}

__global__ __launch_bounds__(256, 7)
void hetero_score_kernel(const float* __restrict__ h_user,
                         const float* __restrict__ h_item,
                         const int* __restrict__ src_clicks,
                         const int* __restrict__ dst_clicks,
                         const int* __restrict__ src_clickedby,
                         const int* __restrict__ dst_clickedby,
                         const int* __restrict__ src_follows,
                         const int* __restrict__ dst_follows,
                         float* __restrict__ out,
                         int E)
{
    const int lane = threadIdx.x & 31;
    const int warp = threadIdx.x >> 5;
    const int sub  = lane & 7;          // lane within edge group
    const int grp  = lane >> 3;         // edge group 0..3 within warp

    const int e = (blockIdx.x * 8 + warp) * 4 + grp;

    const int et = blockIdx.y;

    const float* __restrict__ h_src;
    const float* __restrict__ h_dst;
    const int* __restrict__ src;
    const int* __restrict__ dst;

    if (et == 0) {        // clicks: user -> item
        h_src = h_user;  src = src_clicks;
        h_dst = h_item;  dst = dst_clicks;
    } else if (et == 1) { // clickedby: item -> user
        h_src = h_item;  src = src_clickedby;
        h_dst = h_user;  dst = dst_clickedby;
    } else {              // follows: user -> user
        h_src = h_user;  src = src_follows;
        h_dst = h_user;  dst = dst_follows;
    }

    float s = 0.0f;

    if (e < E) {
        const long long si = (long long)__ldcs(src + e);
        const long long di = (long long)__ldcs(dst + e);

        const float4* a = reinterpret_cast<const float4*>(h_src + si * 128);
        const float4* b = reinterpret_cast<const float4*>(h_dst + di * 128);

        // Issue all 8 independent loads up front (MLP = 8).
        const float4 a0 = __ldg(a + sub);
        const float4 a1 = __ldg(a + sub + 8);
        const float4 a2 = __ldg(a + sub + 16);
        const float4 a3 = __ldg(a + sub + 24);
        const float4 b0 = __ldg(b + sub);
        const float4 b1 = __ldg(b + sub + 8);
        const float4 b2 = __ldg(b + sub + 16);
        const float4 b3 = __ldg(b + sub + 24);

        // Two accumulators for FMA ILP.
        float s0 = a0.x * b0.x;
        float s1 = a1.x * b1.x;
        s0 = fmaf(a0.y, b0.y, s0);
        s1 = fmaf(a1.y, b1.y, s1);
        s0 = fmaf(a0.z, b0.z, s0);
        s1 = fmaf(a1.z, b1.z, s1);
        s0 = fmaf(a0.w, b0.w, s0);
        s1 = fmaf(a1.w, b1.w, s1);
        s0 = fmaf(a2.x, b2.x, s0);
        s1 = fmaf(a3.x, b3.x, s1);
        s0 = fmaf(a2.y, b2.y, s0);
        s1 = fmaf(a3.y, b3.y, s1);
        s0 = fmaf(a2.z, b2.z, s0);
        s1 = fmaf(a3.z, b3.z, s1);
        s0 = fmaf(a2.w, b2.w, s0);
        s1 = fmaf(a3.w, b3.w, s1);
        s = s0 + s1;
    }

    // 3-step butterfly within each 8-lane group; one SHFL per step serves
    // all 4 edges of the warp.
    s += __shfl_xor_sync(0xFFFFFFFFu, s, 4);
    s += __shfl_xor_sync(0xFFFFFFFFu, s, 2);
    s += __shfl_xor_sync(0xFFFFFFFFu, s, 1);

    if (sub == 0 && e < E)
        stg_stream_f32(out + (long long)et * E + e, s);
}

extern "C" void kernel_launch(void* const* d_in, const int* in_sizes, int n_in,
                              void* d_out, int out_size)
{
    const float* h_user        = (const float*)d_in[0];
    const float* h_item        = (const float*)d_in[1];
    const int*   src_clicks    = (const int*)d_in[2];
    const int*   dst_clicks    = (const int*)d_in[3];
    const int*   src_clickedby = (const int*)d_in[4];
    const int*   dst_clickedby = (const int*)d_in[5];
    const int*   src_follows   = (const int*)d_in[6];
    const int*   dst_follows   = (const int*)d_in[7];
    float* out = (float*)d_out;

    const int E = in_sizes[2];                 // 500000 edges per etype
    const int edges_per_block = 32;            // 8 warps * 4 edges
    const int blocks_x = (E + edges_per_block - 1) / edges_per_block;

    dim3 grid(blocks_x, 3, 1);
    hetero_score_kernel<<<grid, 256>>>(h_user, h_item,
                                       src_clicks, dst_clicks,
                                       src_clickedby, dst_clickedby,
                                       src_follows, dst_follows,
                                       out, E);
}